// round 6
// baseline (speedup 1.0000x reference)
#include <cuda_runtime.h>
#include <cuda_bf16.h>
#include <math.h>
#include <stdint.h>

#define S_LEN 1024
#define D_MODEL 4096
#define FF_DIM 14336
#define KVDIM 1024
#define N_HEADS 32
#define N_KV_HEADS 8
#define HEAD_DIM 128

// ---------------- scratch (static device globals; no allocation) ----------------
__device__ float g_h[S_LEN * D_MODEL];
__device__ float g_q[S_LEN * D_MODEL];
__device__ float g_k[S_LEN * KVDIM];
__device__ float g_v[S_LEN * KVDIM];
__device__ float g_attn[S_LEN * D_MODEL];
__device__ float g_res1[S_LEN * D_MODEL];
__device__ float g_f[S_LEN * D_MODEL];
__device__ float g_gate[S_LEN * FF_DIM];
__device__ float g_up[S_LEN * FF_DIM];
__device__ float g_t0[S_LEN * 16];
__device__ float g_t1[S_LEN * 16];
__device__ float g_t2[S_LEN * 16];

// ---------------- rmsnorm ----------------
__global__ void rmsnorm_kernel(const float* __restrict__ x, const float* __restrict__ w,
                               float* __restrict__ o, int D) {
    int row = blockIdx.x;
    const float* xr = x + (size_t)row * D;
    float* orow = o + (size_t)row * D;
    float ss = 0.f;
    for (int c = threadIdx.x; c < D; c += blockDim.x) {
        float v = xr[c];
        ss += v * v;
    }
    __shared__ float sred[32];
    for (int off = 16; off; off >>= 1) ss += __shfl_xor_sync(0xffffffffu, ss, off);
    if ((threadIdx.x & 31) == 0) sred[threadIdx.x >> 5] = ss;
    __syncthreads();
    if (threadIdx.x < 32) {
        float v = (threadIdx.x < (blockDim.x >> 5)) ? sred[threadIdx.x] : 0.f;
        for (int off = 16; off; off >>= 1) v += __shfl_xor_sync(0xffffffffu, v, off);
        if (threadIdx.x == 0) sred[0] = v;
    }
    __syncthreads();
    float inv = rsqrtf(sred[0] / (float)D + 1e-5f);
    for (int c = threadIdx.x; c < D; c += blockDim.x)
        orow[c] = xr[c] * inv * w[c];
}

// ---------------- LoRA down-projection: T[M,16] = X[M,K] @ A[16,K]^T ----------------
__global__ void lora_a_kernel(const float* __restrict__ X, const float* __restrict__ A,
                              float* __restrict__ T, int K) {
    int m = blockIdx.x;
    int t = threadIdx.x;       // 128 threads
    int n = t >> 3;            // 0..15
    int kl = t & 7;
    const float4* xr = (const float4*)(X + (size_t)m * K);
    const float4* ar = (const float4*)(A + (size_t)n * K);
    float ax = 0.f, ay = 0.f, az = 0.f, aw = 0.f;
    int K4 = K >> 2;
    for (int k = kl; k < K4; k += 8) {
        float4 x = xr[k];
        float4 a = ar[k];
        ax += x.x * a.x; ay += x.y * a.y; az += x.z * a.z; aw += x.w * a.w;
    }
    float s = (ax + ay) + (az + aw);
    s += __shfl_xor_sync(0xffffffffu, s, 1);
    s += __shfl_xor_sync(0xffffffffu, s, 2);
    s += __shfl_xor_sync(0xffffffffu, s, 4);
    if (kl == 0) T[m * 16 + n] = s;
}

// ================= bf16 split-3 tensor-core GEMM =================
// C[M,N] = A[M,K] @ B[N,K]^T  (+ 2*T@LB^T)  (+ resid)
// BM=BN=128, BK=32, 256 threads (8 warps, 2x4), warp tile 64x32.
// fp32 inputs split into bf16 hi+lo; acc += Ahi*Bhi + Ahi*Blo + Alo*Bhi.

#define TS_A 40          // padded smem row stride in bf16 elems (80B, 16B-mult)
#define STG_ELEMS (4 * 128 * TS_A)      // hi/lo A + hi/lo B per stage, elems
#define STG_BYTES (STG_ELEMS * 2)       // 40960
#define AHI_OFF 0
#define ALO_OFF (128 * TS_A)
#define BHI_OFF (2 * 128 * TS_A)
#define BLO_OFF (3 * 128 * TS_A)
#define GEMM_SMEM_BYTES (2 * STG_BYTES + 2 * 128 * 16 * 4)   // 98304

__device__ __forceinline__ uint32_t smem_u32(const void* p) {
    return (uint32_t)__cvta_generic_to_shared(p);
}

__device__ __forceinline__ uint32_t pack2(__nv_bfloat16 a, __nv_bfloat16 b) {
    uint16_t ra = *(uint16_t*)&a, rb = *(uint16_t*)&b;
    return (uint32_t)ra | ((uint32_t)rb << 16);
}

__device__ __forceinline__ void ldsm4(uint32_t* r, uint32_t addr) {
    asm volatile("ldmatrix.sync.aligned.m8n8.x4.shared.b16 {%0,%1,%2,%3}, [%4];"
                 : "=r"(r[0]), "=r"(r[1]), "=r"(r[2]), "=r"(r[3]) : "r"(addr));
}

__device__ __forceinline__ void mma_bf16(float* c, const uint32_t* a, const uint32_t* b) {
    asm volatile("mma.sync.aligned.m16n8k16.row.col.f32.bf16.bf16.f32 "
                 "{%0,%1,%2,%3}, {%4,%5,%6,%7}, {%8,%9}, {%0,%1,%2,%3};"
                 : "+f"(c[0]), "+f"(c[1]), "+f"(c[2]), "+f"(c[3])
                 : "r"(a[0]), "r"(a[1]), "r"(a[2]), "r"(a[3]), "r"(b[0]), "r"(b[1]));
}

__device__ __forceinline__ void cvt_store8(__nv_bfloat16* hi_p, __nv_bfloat16* lo_p, float4 v) {
    __nv_bfloat16 h0 = __float2bfloat16_rn(v.x);
    __nv_bfloat16 h1 = __float2bfloat16_rn(v.y);
    __nv_bfloat16 h2 = __float2bfloat16_rn(v.z);
    __nv_bfloat16 h3 = __float2bfloat16_rn(v.w);
    __nv_bfloat16 l0 = __float2bfloat16_rn(v.x - __bfloat162float(h0));
    __nv_bfloat16 l1 = __float2bfloat16_rn(v.y - __bfloat162float(h1));
    __nv_bfloat16 l2 = __float2bfloat16_rn(v.z - __bfloat162float(h2));
    __nv_bfloat16 l3 = __float2bfloat16_rn(v.w - __bfloat162float(h3));
    uint2 wh; wh.x = pack2(h0, h1); wh.y = pack2(h2, h3);
    uint2 wl; wl.x = pack2(l0, l1); wl.y = pack2(l2, l3);
    *(uint2*)hi_p = wh;
    *(uint2*)lo_p = wl;
}

__global__ void __launch_bounds__(256) sgemm_lora(
    const float* __restrict__ A, const float* __restrict__ B, float* __restrict__ C,
    int M, int N, int K,
    const float* __restrict__ T, const float* __restrict__ LB,
    const float* __restrict__ resid) {
    extern __shared__ char smem_raw[];
    __nv_bfloat16* sB16 = (__nv_bfloat16*)smem_raw;
    float* Ts = (float*)(smem_raw + 2 * STG_BYTES);
    float* LBs = Ts + 128 * 16;

    int tid = threadIdx.x;
    int lane = tid & 31, warp = tid >> 5;
    int m0 = blockIdx.y * 128;
    int n0 = blockIdx.x * 128;

    if (T != nullptr) {
        for (int i = tid; i < 128 * 4; i += 256) {
            int r = i >> 2, c = (i & 3) * 4;
            *(float4*)&Ts[r * 16 + c]  = *(const float4*)&T[(size_t)(m0 + r) * 16 + c];
            *(float4*)&LBs[r * 16 + c] = *(const float4*)&LB[(size_t)(n0 + r) * 16 + c];
        }
    }

    // gmem load mapping: 4 float4 per tile (A and B each)
    int glr = tid >> 3;            // 0..31 row group
    int glk = (tid & 7) * 4;       // float4 k offset

    // ldmatrix lane mapping
    int wm = (warp >> 2) * 64;
    int wn = (warp & 3) * 32;
    int a_row = wm + (lane & 15);
    int a_kof = (lane >> 4) << 3;
    int b_row = wn + (lane & 7) + ((lane >> 4) << 3);
    int b_kof = ((lane >> 3) & 1) << 3;

    uint32_t sbase = smem_u32(smem_raw);

    float acc[4][4][4];
#pragma unroll
    for (int i = 0; i < 4; i++)
#pragma unroll
        for (int j = 0; j < 4; j++)
#pragma unroll
            for (int e = 0; e < 4; e++) acc[i][j][e] = 0.f;

    float4 av[4], bv[4];

    // preload k0 = 0
#pragma unroll
    for (int i = 0; i < 4; i++) {
        av[i] = *(const float4*)&A[(size_t)(m0 + glr + 32 * i) * K + glk];
        bv[i] = *(const float4*)&B[(size_t)(n0 + glr + 32 * i) * K + glk];
    }
    {
        __nv_bfloat16* sa = sB16;  // stage 0
#pragma unroll
        for (int i = 0; i < 4; i++) {
            int off = (glr + 32 * i) * TS_A + glk;
            cvt_store8(sa + AHI_OFF + off, sa + ALO_OFF + off, av[i]);
            cvt_store8(sa + BHI_OFF + off, sa + BLO_OFF + off, bv[i]);
        }
    }
    __syncthreads();

    int s = 0;
    for (int k0 = 0; k0 < K; k0 += 32) {
        bool more = (k0 + 32 < K);
        if (more) {
#pragma unroll
            for (int i = 0; i < 4; i++) {
                av[i] = *(const float4*)&A[(size_t)(m0 + glr + 32 * i) * K + k0 + 32 + glk];
                bv[i] = *(const float4*)&B[(size_t)(n0 + glr + 32 * i) * K + k0 + 32 + glk];
            }
        }

        // compute on stage s
        uint32_t sgbase = sbase + (uint32_t)s * STG_BYTES;
#pragma unroll
        for (int kk = 0; kk < 32; kk += 16) {
            uint32_t ahi[4][4], alo[4][4], bhi[2][4], blo[2][4];
#pragma unroll
            for (int mi = 0; mi < 4; mi++) {
                uint32_t off = ((uint32_t)(a_row + 16 * mi) * TS_A + kk + a_kof) * 2;
                ldsm4(ahi[mi], sgbase + AHI_OFF * 2 + off);
                ldsm4(alo[mi], sgbase + ALO_OFF * 2 + off);
            }
#pragma unroll
            for (int j = 0; j < 2; j++) {
                uint32_t off = ((uint32_t)(b_row + 16 * j) * TS_A + kk + b_kof) * 2;
                ldsm4(bhi[j], sgbase + BHI_OFF * 2 + off);
                ldsm4(blo[j], sgbase + BLO_OFF * 2 + off);
            }
            // term 1: hi*hi
#pragma unroll
            for (int mi = 0; mi < 4; mi++)
#pragma unroll
                for (int nt = 0; nt < 4; nt++)
                    mma_bf16(acc[mi][nt], ahi[mi], &bhi[nt >> 1][(nt & 1) * 2]);
            // term 2: hi*lo
#pragma unroll
            for (int mi = 0; mi < 4; mi++)
#pragma unroll
                for (int nt = 0; nt < 4; nt++)
                    mma_bf16(acc[mi][nt], ahi[mi], &blo[nt >> 1][(nt & 1) * 2]);
            // term 3: lo*hi
#pragma unroll
            for (int mi = 0; mi < 4; mi++)
#pragma unroll
                for (int nt = 0; nt < 4; nt++)
                    mma_bf16(acc[mi][nt], alo[mi], &bhi[nt >> 1][(nt & 1) * 2]);
        }

        if (more) {
            __nv_bfloat16* sa = sB16 + (s ^ 1) * STG_ELEMS;
#pragma unroll
            for (int i = 0; i < 4; i++) {
                int off = (glr + 32 * i) * TS_A + glk;
                cvt_store8(sa + AHI_OFF + off, sa + ALO_OFF + off, av[i]);
                cvt_store8(sa + BHI_OFF + off, sa + BLO_OFF + off, bv[i]);
            }
        }
        __syncthreads();
        s ^= 1;
    }

    // ---- LoRA rank-16 epilogue ----
    int rg = lane >> 2;           // row within 8
    int cg = (lane & 3) * 2;      // col within 8
    if (T != nullptr) {
#pragma unroll
        for (int r = 0; r < 16; r++) {
            float tm[8], tn[8];
#pragma unroll
            for (int mi = 0; mi < 4; mi++) {
                tm[mi * 2 + 0] = 2.0f * Ts[(wm + mi * 16 + rg) * 16 + r];
                tm[mi * 2 + 1] = 2.0f * Ts[(wm + mi * 16 + rg + 8) * 16 + r];
            }
#pragma unroll
            for (int nt = 0; nt < 4; nt++) {
                tn[nt * 2 + 0] = LBs[(wn + nt * 8 + cg) * 16 + r];
                tn[nt * 2 + 1] = LBs[(wn + nt * 8 + cg + 1) * 16 + r];
            }
#pragma unroll
            for (int mi = 0; mi < 4; mi++)
#pragma unroll
                for (int nt = 0; nt < 4; nt++) {
                    acc[mi][nt][0] += tm[mi * 2 + 0] * tn[nt * 2 + 0];
                    acc[mi][nt][1] += tm[mi * 2 + 0] * tn[nt * 2 + 1];
                    acc[mi][nt][2] += tm[mi * 2 + 1] * tn[nt * 2 + 0];
                    acc[mi][nt][3] += tm[mi * 2 + 1] * tn[nt * 2 + 1];
                }
        }
    }

    // ---- store (optional residual) ----
#pragma unroll
    for (int mi = 0; mi < 4; mi++) {
#pragma unroll
        for (int p = 0; p < 2; p++) {
            size_t row = (size_t)(m0 + wm + mi * 16 + rg + 8 * p);
#pragma unroll
            for (int nt = 0; nt < 4; nt++) {
                size_t col = n0 + wn + nt * 8 + cg;
                float2 o;
                o.x = acc[mi][nt][p * 2 + 0];
                o.y = acc[mi][nt][p * 2 + 1];
                if (resid != nullptr) {
                    float2 rr = *(const float2*)&resid[row * N + col];
                    o.x += rr.x; o.y += rr.y;
                }
                *(float2*)&C[row * N + col] = o;
            }
        }
    }
}

// ---------------- RoPE (in-place, interleaved pairs) ----------------
__global__ void rope_kernel(float* __restrict__ x, const float* __restrict__ cosb,
                            const float* __restrict__ sinb, int H) {
    int idx = blockIdx.x * blockDim.x + threadIdx.x;
    int total = S_LEN * H * 64;
    if (idx >= total) return;
    int i = idx & 63;
    int sh = idx >> 6;   // s*H + h
    int s = sh / H;
    float c = cosb[s * 64 + i];
    float sn = sinb[s * 64 + i];
    float* p = x + (size_t)sh * 128 + 2 * i;
    float a = p[0], b = p[1];
    p[0] = a * c - b * sn;
    p[1] = a * sn + b * c;
}

// ---------------- causal flash attention (fp32) ----------------
#define QS_STRIDE 129
#define SS_STRIDE 65
#define FLASH_SMEM_FLOATS (64 * QS_STRIDE + 64 * 128 + 64 * 128 + 64 * SS_STRIDE + 3 * 64)
#define FLASH_SMEM_BYTES (FLASH_SMEM_FLOATS * 4)

__global__ void __launch_bounds__(256) flash_attn_kernel(
    const float* __restrict__ Q, const float* __restrict__ K, const float* __restrict__ V,
    float* __restrict__ O) {
    extern __shared__ float smem[];
    float* Qs = smem;
    float* Ks = Qs + 64 * QS_STRIDE;
    float* Vs = Ks + 64 * 128;
    float* Ss = Vs + 64 * 128;
    float* rowm = Ss + 64 * SS_STRIDE;
    float* rowl = rowm + 64;
    float* rowscale = rowl + 64;

    int h = blockIdx.x;
    int qb = blockIdx.y;
    int kvh = h >> 2;
    int tid = threadIdx.x;
    int q0 = qb * 64;

    for (int i = tid; i < 64 * 128; i += 256) {
        int r = i >> 7, c = i & 127;
        Qs[r * QS_STRIDE + c] = Q[(size_t)(q0 + r) * D_MODEL + h * HEAD_DIM + c];
    }
    if (tid < 64) { rowm[tid] = -1e30f; rowl[tid] = 0.f; }

    int q = tid & 63;
    int kbase = (tid >> 6) * 16;
    int d0 = (tid >> 6) * 32;
    float acc[32];
#pragma unroll
    for (int d = 0; d < 32; d++) acc[d] = 0.f;

    for (int kb = 0; kb <= qb; kb++) {
        int k0 = kb * 64;
        __syncthreads();
        for (int i = tid; i < 64 * 32; i += 256) {
            int r = i >> 5, c4 = (i & 31) * 4;
            *(float4*)&Ks[r * 128 + c4] = *(const float4*)&K[(size_t)(k0 + r) * KVDIM + kvh * HEAD_DIM + c4];
            *(float4*)&Vs[r * 128 + c4] = *(const float4*)&V[(size_t)(k0 + r) * KVDIM + kvh * HEAD_DIM + c4];
        }
        __syncthreads();

        float sc[16];
#pragma unroll
        for (int j = 0; j < 16; j++) sc[j] = 0.f;
        for (int d = 0; d < 128; d++) {
            float qv = Qs[q * QS_STRIDE + d];
#pragma unroll
            for (int j = 0; j < 16; j++) sc[j] += qv * Ks[(kbase + j) * 128 + d];
        }
        const float scale = 0.08838834764831845f;
#pragma unroll
        for (int j = 0; j < 16; j++) {
            int kk = kbase + j;
            float sv = sc[j] * scale;
            if (kb == qb && (k0 + kk) > (q0 + q)) sv = -1e9f;
            Ss[q * SS_STRIDE + kk] = sv;
        }
        __syncthreads();

        if (tid < 64) {
            float m_old = rowm[tid], m = m_old;
            for (int kk = 0; kk < 64; kk++) m = fmaxf(m, Ss[tid * SS_STRIDE + kk]);
            float corr = __expf(m_old - m);
            float l = rowl[tid] * corr;
            for (int kk = 0; kk < 64; kk++) {
                float p = __expf(Ss[tid * SS_STRIDE + kk] - m);
                Ss[tid * SS_STRIDE + kk] = p;
                l += p;
            }
            rowm[tid] = m; rowl[tid] = l; rowscale[tid] = corr;
        }
        __syncthreads();

        float corr = rowscale[q];
#pragma unroll
        for (int d = 0; d < 32; d++) acc[d] *= corr;
        for (int kk = 0; kk < 64; kk++) {
            float p = Ss[q * SS_STRIDE + kk];
#pragma unroll
            for (int d = 0; d < 32; d++) acc[d] += p * Vs[kk * 128 + d0 + d];
        }
    }

    float inv = 1.f / rowl[q];
    float* orow = O + (size_t)(q0 + q) * D_MODEL + h * HEAD_DIM + d0;
#pragma unroll
    for (int d = 0; d < 32; d++) orow[d] = acc[d] * inv;
}

// ---------------- silu(gate) * up ----------------
__global__ void silu_mul_kernel(const float* __restrict__ g, const float* __restrict__ u,
                                float* __restrict__ o, int n) {
    int i = blockIdx.x * blockDim.x + threadIdx.x;
    if (i < n) {
        float x = g[i];
        float s = x / (1.f + __expf(-x));
        o[i] = s * u[i];
    }
}

// ---------------- launch ----------------
extern "C" void kernel_launch(void* const* d_in, const int* in_sizes, int n_in,
                              void* d_out, int out_size) {
    const float* data = (const float*)d_in[0];
    const float* cosb = (const float*)d_in[2];
    const float* sinb = (const float*)d_in[3];
    const float* attn_norm_w = (const float*)d_in[4];
    const float* wq = (const float*)d_in[5];
    const float* wk = (const float*)d_in[6];
    const float* wv = (const float*)d_in[7];
    const float* wo = (const float*)d_in[8];
    const float* wq_a = (const float*)d_in[9];
    const float* wq_b = (const float*)d_in[10];
    const float* wk_a = (const float*)d_in[11];
    const float* wk_b = (const float*)d_in[12];
    const float* wv_a = (const float*)d_in[13];
    const float* wv_b = (const float*)d_in[14];
    const float* wo_a = (const float*)d_in[15];
    const float* wo_b = (const float*)d_in[16];
    const float* ffn_norm_w = (const float*)d_in[17];
    const float* w1 = (const float*)d_in[18];
    const float* w2 = (const float*)d_in[19];
    const float* w3 = (const float*)d_in[20];
    const float* w1_a = (const float*)d_in[21];
    const float* w1_b = (const float*)d_in[22];
    const float* w2_a = (const float*)d_in[23];
    const float* w2_b = (const float*)d_in[24];
    const float* w3_a = (const float*)d_in[25];
    const float* w3_b = (const float*)d_in[26];
    float* out = (float*)d_out;

    float *h, *q, *k, *v, *attn, *res1, *f, *gate, *up, *t0, *t1, *t2;
    cudaGetSymbolAddress((void**)&h, g_h);
    cudaGetSymbolAddress((void**)&q, g_q);
    cudaGetSymbolAddress((void**)&k, g_k);
    cudaGetSymbolAddress((void**)&v, g_v);
    cudaGetSymbolAddress((void**)&attn, g_attn);
    cudaGetSymbolAddress((void**)&res1, g_res1);
    cudaGetSymbolAddress((void**)&f, g_f);
    cudaGetSymbolAddress((void**)&gate, g_gate);
    cudaGetSymbolAddress((void**)&up, g_up);
    cudaGetSymbolAddress((void**)&t0, g_t0);
    cudaGetSymbolAddress((void**)&t1, g_t1);
    cudaGetSymbolAddress((void**)&t2, g_t2);

    cudaFuncSetAttribute(flash_attn_kernel, cudaFuncAttributeMaxDynamicSharedMemorySize,
                         FLASH_SMEM_BYTES);
    cudaFuncSetAttribute(sgemm_lora, cudaFuncAttributeMaxDynamicSharedMemorySize,
                         GEMM_SMEM_BYTES);

    // 1) attn rmsnorm
    rmsnorm_kernel<<<S_LEN, 256>>>(data, attn_norm_w, h, D_MODEL);

    // 2) q/k/v projections with fused LoRA
    lora_a_kernel<<<S_LEN, 128>>>(h, wq_a, t0, D_MODEL);
    lora_a_kernel<<<S_LEN, 128>>>(h, wk_a, t1, D_MODEL);
    lora_a_kernel<<<S_LEN, 128>>>(h, wv_a, t2, D_MODEL);
    sgemm_lora<<<dim3(D_MODEL / 128, S_LEN / 128), 256, GEMM_SMEM_BYTES>>>(h, wq, q, S_LEN, D_MODEL, D_MODEL, t0, wq_b, nullptr);
    sgemm_lora<<<dim3(KVDIM / 128, S_LEN / 128), 256, GEMM_SMEM_BYTES>>>(h, wk, k, S_LEN, KVDIM, D_MODEL, t1, wk_b, nullptr);
    sgemm_lora<<<dim3(KVDIM / 128, S_LEN / 128), 256, GEMM_SMEM_BYTES>>>(h, wv, v, S_LEN, KVDIM, D_MODEL, t2, wv_b, nullptr);

    // 3) RoPE
    rope_kernel<<<(S_LEN * N_HEADS * 64) / 256, 256>>>(q, cosb, sinb, N_HEADS);
    rope_kernel<<<(S_LEN * N_KV_HEADS * 64) / 256, 256>>>(k, cosb, sinb, N_KV_HEADS);

    // 4) attention
    flash_attn_kernel<<<dim3(N_HEADS, S_LEN / 64), 256, FLASH_SMEM_BYTES>>>(q, k, v, attn);

    // 5) output projection + residual
    lora_a_kernel<<<S_LEN, 128>>>(attn, wo_a, t0, D_MODEL);
    sgemm_lora<<<dim3(D_MODEL / 128, S_LEN / 128), 256, GEMM_SMEM_BYTES>>>(attn, wo, res1, S_LEN, D_MODEL, D_MODEL, t0, wo_b, data);

    // 6) ffn rmsnorm
    rmsnorm_kernel<<<S_LEN, 256>>>(res1, ffn_norm_w, f, D_MODEL);

    // 7) gate / up
    lora_a_kernel<<<S_LEN, 128>>>(f, w1_a, t0, D_MODEL);
    lora_a_kernel<<<S_LEN, 128>>>(f, w3_a, t1, D_MODEL);
    sgemm_lora<<<dim3(FF_DIM / 128, S_LEN / 128), 256, GEMM_SMEM_BYTES>>>(f, w1, gate, S_LEN, FF_DIM, D_MODEL, t0, w1_b, nullptr);
    sgemm_lora<<<dim3(FF_DIM / 128, S_LEN / 128), 256, GEMM_SMEM_BYTES>>>(f, w3, up, S_LEN, FF_DIM, D_MODEL, t1, w3_b, nullptr);

    // 8) silu * up (in place into gate)
    silu_mul_kernel<<<(S_LEN * FF_DIM) / 256, 256>>>(gate, up, gate, S_LEN * FF_DIM);

    // 9) down projection + residual -> out
    lora_a_kernel<<<S_LEN, 128>>>(gate, w2_a, t0, FF_DIM);
    sgemm_lora<<<dim3(D_MODEL / 128, S_LEN / 128), 256, GEMM_SMEM_BYTES>>>(gate, w2, out, S_LEN, D_MODEL, FF_DIM, t0, w2_b, res1);
}

// round 12
// speedup vs baseline: 1.0569x; 1.0569x over previous
#include <cuda_runtime.h>
#include <cuda_bf16.h>
#include <math.h>
#include <stdint.h>

#define S_LEN 1024
#define D_MODEL 4096
#define FF_DIM 14336
#define KVDIM 1024
#define N_HEADS 32
#define N_KV_HEADS 8
#define HEAD_DIM 128

// ---------------- scratch (static device globals; no allocation) ----------------
__device__ float g_h[S_LEN * D_MODEL];
__device__ float g_q[S_LEN * D_MODEL];
__device__ float g_k[S_LEN * KVDIM];
__device__ float g_v[S_LEN * KVDIM];
__device__ float g_attn[S_LEN * D_MODEL];
__device__ float g_res1[S_LEN * D_MODEL];
__device__ float g_f[S_LEN * D_MODEL];
__device__ float g_gate[S_LEN * FF_DIM];
__device__ float g_up[S_LEN * FF_DIM];
__device__ float g_t0[S_LEN * 16];
__device__ float g_t1[S_LEN * 16];
__device__ float g_t2[S_LEN * 16];

// ================= shared helpers =================
__device__ __forceinline__ uint32_t smem_u32(const void* p) {
    return (uint32_t)__cvta_generic_to_shared(p);
}
__device__ __forceinline__ uint32_t pack2(__nv_bfloat16 a, __nv_bfloat16 b) {
    uint16_t ra = *(uint16_t*)&a, rb = *(uint16_t*)&b;
    return (uint32_t)ra | ((uint32_t)rb << 16);
}
__device__ __forceinline__ void ldsm4(uint32_t* r, uint32_t addr) {
    asm volatile("ldmatrix.sync.aligned.m8n8.x4.shared.b16 {%0,%1,%2,%3}, [%4];"
                 : "=r"(r[0]), "=r"(r[1]), "=r"(r[2]), "=r"(r[3]) : "r"(addr));
}
__device__ __forceinline__ void mma_bf16(float* c, const uint32_t* a, const uint32_t* b) {
    asm volatile("mma.sync.aligned.m16n8k16.row.col.f32.bf16.bf16.f32 "
                 "{%0,%1,%2,%3}, {%4,%5,%6,%7}, {%8,%9}, {%0,%1,%2,%3};"
                 : "+f"(c[0]), "+f"(c[1]), "+f"(c[2]), "+f"(c[3])
                 : "r"(a[0]), "r"(a[1]), "r"(a[2]), "r"(a[3]), "r"(b[0]), "r"(b[1]));
}
__device__ __forceinline__ void cvt_store8(__nv_bfloat16* hi_p, __nv_bfloat16* lo_p, float4 v) {
    __nv_bfloat16 h0 = __float2bfloat16_rn(v.x);
    __nv_bfloat16 h1 = __float2bfloat16_rn(v.y);
    __nv_bfloat16 h2 = __float2bfloat16_rn(v.z);
    __nv_bfloat16 h3 = __float2bfloat16_rn(v.w);
    __nv_bfloat16 l0 = __float2bfloat16_rn(v.x - __bfloat162float(h0));
    __nv_bfloat16 l1 = __float2bfloat16_rn(v.y - __bfloat162float(h1));
    __nv_bfloat16 l2 = __float2bfloat16_rn(v.z - __bfloat162float(h2));
    __nv_bfloat16 l3 = __float2bfloat16_rn(v.w - __bfloat162float(h3));
    uint2 wh; wh.x = pack2(h0, h1); wh.y = pack2(h2, h3);
    uint2 wl; wl.x = pack2(l0, l1); wl.y = pack2(l2, l3);
    *(uint2*)hi_p = wh;
    *(uint2*)lo_p = wl;
}
__device__ __forceinline__ void split_pair(float a, float b, uint32_t* hi, uint32_t* lo) {
    __nv_bfloat16 ha = __float2bfloat16_rn(a), hb = __float2bfloat16_rn(b);
    __nv_bfloat16 la = __float2bfloat16_rn(a - __bfloat162float(ha));
    __nv_bfloat16 lb = __float2bfloat16_rn(b - __bfloat162float(hb));
    *hi = pack2(ha, hb);
    *lo = pack2(la, lb);
}

// ---------------- rmsnorm ----------------
__global__ void rmsnorm_kernel(const float* __restrict__ x, const float* __restrict__ w,
                               float* __restrict__ o, int D) {
    int row = blockIdx.x;
    const float* xr = x + (size_t)row * D;
    float* orow = o + (size_t)row * D;
    float ss = 0.f;
    for (int c = threadIdx.x; c < D; c += blockDim.x) {
        float v = xr[c];
        ss += v * v;
    }
    __shared__ float sred[32];
    for (int off = 16; off; off >>= 1) ss += __shfl_xor_sync(0xffffffffu, ss, off);
    if ((threadIdx.x & 31) == 0) sred[threadIdx.x >> 5] = ss;
    __syncthreads();
    if (threadIdx.x < 32) {
        float v = (threadIdx.x < (blockDim.x >> 5)) ? sred[threadIdx.x] : 0.f;
        for (int off = 16; off; off >>= 1) v += __shfl_xor_sync(0xffffffffu, v, off);
        if (threadIdx.x == 0) sred[0] = v;
    }
    __syncthreads();
    float inv = rsqrtf(sred[0] / (float)D + 1e-5f);
    for (int c = threadIdx.x; c < D; c += blockDim.x)
        orow[c] = xr[c] * inv * w[c];
}

// ---------------- LoRA down-projection: T[M,16] = X[M,K] @ A[16,K]^T ----------------
__global__ void lora_a_kernel(const float* __restrict__ X, const float* __restrict__ A,
                              float* __restrict__ T, int K) {
    int m = blockIdx.x;
    int t = threadIdx.x;       // 128 threads
    int n = t >> 3;            // 0..15
    int kl = t & 7;
    const float4* xr = (const float4*)(X + (size_t)m * K);
    const float4* ar = (const float4*)(A + (size_t)n * K);
    float ax = 0.f, ay = 0.f, az = 0.f, aw = 0.f;
    int K4 = K >> 2;
    for (int k = kl; k < K4; k += 8) {
        float4 x = xr[k];
        float4 a = ar[k];
        ax += x.x * a.x; ay += x.y * a.y; az += x.z * a.z; aw += x.w * a.w;
    }
    float s = (ax + ay) + (az + aw);
    s += __shfl_xor_sync(0xffffffffu, s, 1);
    s += __shfl_xor_sync(0xffffffffu, s, 2);
    s += __shfl_xor_sync(0xffffffffu, s, 4);
    if (kl == 0) T[m * 16 + n] = s;
}

// ================= bf16 split-3 tensor-core GEMM (unchanged, at HMMA floor) =============
#define TS_A 40
#define STG_ELEMS (4 * 128 * TS_A)
#define STG_BYTES (STG_ELEMS * 2)
#define AHI_OFF 0
#define ALO_OFF (128 * TS_A)
#define BHI_OFF (2 * 128 * TS_A)
#define BLO_OFF (3 * 128 * TS_A)
#define GEMM_SMEM_BYTES (2 * STG_BYTES + 2 * 128 * 16 * 4)

__global__ void __launch_bounds__(256) sgemm_lora(
    const float* __restrict__ A, const float* __restrict__ B, float* __restrict__ C,
    int M, int N, int K,
    const float* __restrict__ T, const float* __restrict__ LB,
    const float* __restrict__ resid) {
    extern __shared__ char smem_raw[];
    __nv_bfloat16* sB16 = (__nv_bfloat16*)smem_raw;
    float* Ts = (float*)(smem_raw + 2 * STG_BYTES);
    float* LBs = Ts + 128 * 16;

    int tid = threadIdx.x;
    int lane = tid & 31, warp = tid >> 5;
    int m0 = blockIdx.y * 128;
    int n0 = blockIdx.x * 128;

    if (T != nullptr) {
        for (int i = tid; i < 128 * 4; i += 256) {
            int r = i >> 2, c = (i & 3) * 4;
            *(float4*)&Ts[r * 16 + c]  = *(const float4*)&T[(size_t)(m0 + r) * 16 + c];
            *(float4*)&LBs[r * 16 + c] = *(const float4*)&LB[(size_t)(n0 + r) * 16 + c];
        }
    }

    int glr = tid >> 3;
    int glk = (tid & 7) * 4;

    int wm = (warp >> 2) * 64;
    int wn = (warp & 3) * 32;
    int a_row = wm + (lane & 15);
    int a_kof = (lane >> 4) << 3;
    int b_row = wn + (lane & 7) + ((lane >> 4) << 3);
    int b_kof = ((lane >> 3) & 1) << 3;

    uint32_t sbase = smem_u32(smem_raw);

    float acc[4][4][4];
#pragma unroll
    for (int i = 0; i < 4; i++)
#pragma unroll
        for (int j = 0; j < 4; j++)
#pragma unroll
            for (int e = 0; e < 4; e++) acc[i][j][e] = 0.f;

    float4 av[4], bv[4];
#pragma unroll
    for (int i = 0; i < 4; i++) {
        av[i] = *(const float4*)&A[(size_t)(m0 + glr + 32 * i) * K + glk];
        bv[i] = *(const float4*)&B[(size_t)(n0 + glr + 32 * i) * K + glk];
    }
    {
        __nv_bfloat16* sa = sB16;
#pragma unroll
        for (int i = 0; i < 4; i++) {
            int off = (glr + 32 * i) * TS_A + glk;
            cvt_store8(sa + AHI_OFF + off, sa + ALO_OFF + off, av[i]);
            cvt_store8(sa + BHI_OFF + off, sa + BLO_OFF + off, bv[i]);
        }
    }
    __syncthreads();

    int s = 0;
    for (int k0 = 0; k0 < K; k0 += 32) {
        bool more = (k0 + 32 < K);
        if (more) {
#pragma unroll
            for (int i = 0; i < 4; i++) {
                av[i] = *(const float4*)&A[(size_t)(m0 + glr + 32 * i) * K + k0 + 32 + glk];
                bv[i] = *(const float4*)&B[(size_t)(n0 + glr + 32 * i) * K + k0 + 32 + glk];
            }
        }
        uint32_t sgbase = sbase + (uint32_t)s * STG_BYTES;
#pragma unroll
        for (int kk = 0; kk < 32; kk += 16) {
            uint32_t ahi[4][4], alo[4][4], bhi[2][4], blo[2][4];
#pragma unroll
            for (int mi = 0; mi < 4; mi++) {
                uint32_t off = ((uint32_t)(a_row + 16 * mi) * TS_A + kk + a_kof) * 2;
                ldsm4(ahi[mi], sgbase + AHI_OFF * 2 + off);
                ldsm4(alo[mi], sgbase + ALO_OFF * 2 + off);
            }
#pragma unroll
            for (int j = 0; j < 2; j++) {
                uint32_t off = ((uint32_t)(b_row + 16 * j) * TS_A + kk + b_kof) * 2;
                ldsm4(bhi[j], sgbase + BHI_OFF * 2 + off);
                ldsm4(blo[j], sgbase + BLO_OFF * 2 + off);
            }
#pragma unroll
            for (int mi = 0; mi < 4; mi++)
#pragma unroll
                for (int nt = 0; nt < 4; nt++)
                    mma_bf16(acc[mi][nt], ahi[mi], &bhi[nt >> 1][(nt & 1) * 2]);
#pragma unroll
            for (int mi = 0; mi < 4; mi++)
#pragma unroll
                for (int nt = 0; nt < 4; nt++)
                    mma_bf16(acc[mi][nt], ahi[mi], &blo[nt >> 1][(nt & 1) * 2]);
#pragma unroll
            for (int mi = 0; mi < 4; mi++)
#pragma unroll
                for (int nt = 0; nt < 4; nt++)
                    mma_bf16(acc[mi][nt], alo[mi], &bhi[nt >> 1][(nt & 1) * 2]);
        }
        if (more) {
            __nv_bfloat16* sa = sB16 + (s ^ 1) * STG_ELEMS;
#pragma unroll
            for (int i = 0; i < 4; i++) {
                int off = (glr + 32 * i) * TS_A + glk;
                cvt_store8(sa + AHI_OFF + off, sa + ALO_OFF + off, av[i]);
                cvt_store8(sa + BHI_OFF + off, sa + BLO_OFF + off, bv[i]);
            }
        }
        __syncthreads();
        s ^= 1;
    }

    int rg = lane >> 2;
    int cg = (lane & 3) * 2;
    if (T != nullptr) {
#pragma unroll
        for (int r = 0; r < 16; r++) {
            float tm[8], tn[8];
#pragma unroll
            for (int mi = 0; mi < 4; mi++) {
                tm[mi * 2 + 0] = 2.0f * Ts[(wm + mi * 16 + rg) * 16 + r];
                tm[mi * 2 + 1] = 2.0f * Ts[(wm + mi * 16 + rg + 8) * 16 + r];
            }
#pragma unroll
            for (int nt = 0; nt < 4; nt++) {
                tn[nt * 2 + 0] = LBs[(wn + nt * 8 + cg) * 16 + r];
                tn[nt * 2 + 1] = LBs[(wn + nt * 8 + cg + 1) * 16 + r];
            }
#pragma unroll
            for (int mi = 0; mi < 4; mi++)
#pragma unroll
                for (int nt = 0; nt < 4; nt++) {
                    acc[mi][nt][0] += tm[mi * 2 + 0] * tn[nt * 2 + 0];
                    acc[mi][nt][1] += tm[mi * 2 + 0] * tn[nt * 2 + 1];
                    acc[mi][nt][2] += tm[mi * 2 + 1] * tn[nt * 2 + 0];
                    acc[mi][nt][3] += tm[mi * 2 + 1] * tn[nt * 2 + 1];
                }
        }
    }

#pragma unroll
    for (int mi = 0; mi < 4; mi++) {
#pragma unroll
        for (int p = 0; p < 2; p++) {
            size_t row = (size_t)(m0 + wm + mi * 16 + rg + 8 * p);
#pragma unroll
            for (int nt = 0; nt < 4; nt++) {
                size_t col = n0 + wn + nt * 8 + cg;
                float2 o;
                o.x = acc[mi][nt][p * 2 + 0];
                o.y = acc[mi][nt][p * 2 + 1];
                if (resid != nullptr) {
                    float2 rr = *(const float2*)&resid[row * N + col];
                    o.x += rr.x; o.y += rr.y;
                }
                *(float2*)&C[row * N + col] = o;
            }
        }
    }
}

// ---------------- RoPE ----------------
__global__ void rope_kernel(float* __restrict__ x, const float* __restrict__ cosb,
                            const float* __restrict__ sinb, int H) {
    int idx = blockIdx.x * blockDim.x + threadIdx.x;
    int total = S_LEN * H * 64;
    if (idx >= total) return;
    int i = idx & 63;
    int sh = idx >> 6;
    int s = sh / H;
    float c = cosb[s * 64 + i];
    float sn = sinb[s * 64 + i];
    float* p = x + (size_t)sh * 128 + 2 * i;
    float a = p[0], b = p[1];
    p[0] = a * c - b * sn;
    p[1] = a * sn + b * c;
}

// ================= tensor-core causal flash attention (bf16 3-term) =================
// BQ=BK=64, D=128. 8 warps: warp_m = wid&3 (16 q rows), warp_n = wid>>2 (k/d half).
// smem bf16 (swizzled): Qh/Ql [64][128], Kh/Kl [64][128], Vth/Vtl [128][64] (V^T),
// Ph/Pl [64][64]; fp32 stats maxp[2][64], sump[2][64].
#define FQH 0
#define FQL 16384
#define FKH 32768
#define FKL 49152
#define FVH 65536
#define FVL 81920
#define FPH 98304
#define FPL 106496
#define FSTAT 114688
#define FLASH_TC_SMEM (114688 + 1024)

__global__ void __launch_bounds__(256) flash_tc(
    const float* __restrict__ Q, const float* __restrict__ K, const float* __restrict__ V,
    float* __restrict__ O) {
    extern __shared__ char smc[];
    uint32_t sb = smem_u32(smc);
    float* maxp = (float*)(smc + FSTAT);   // [2][64]
    float* sump = maxp + 128;              // [2][64]

    int h = blockIdx.x;
    int qb = (gridDim.y - 1) - blockIdx.y;   // long CTAs first
    int kvh = h >> 2;
    int tid = threadIdx.x;
    int lane = tid & 31, wid = tid >> 5;
    int warp_m = wid & 3, warp_n = wid >> 2;
    int q0 = qb * 64;

    int rg = lane >> 2;
    int cg = (lane & 3) * 2;
    int a_row16 = (lane & 15);
    int a_sel = lane >> 4;                  // chunk parity for A frags
    int b_roff = (lane & 7) + ((lane >> 4) << 3);
    int b_sel = (lane >> 3) & 1;

    // ---- load Q tile (fp32 -> hi/lo, swizzled 256B rows) ----
#pragma unroll
    for (int i = 0; i < 8; i++) {
        int u = tid + i * 256;              // 2048 float4 units
        int r = u >> 5;
        int col = (u & 31) * 4;
        float4 v = *(const float4*)&Q[(size_t)(q0 + r) * D_MODEL + h * HEAD_DIM + col];
        uint32_t adr = sb + FQH + r * 256 + ((((col >> 3) ^ (r & 7))) << 4) + (col & 7) * 2;
        __nv_bfloat16 tmp_h[4], tmp_l[4];
        cvt_store8(tmp_h, tmp_l, v);        // pack via helper then write 8B each
        uint2 wh = *(uint2*)tmp_h, wl = *(uint2*)tmp_l;
        asm volatile("st.shared.v2.b32 [%0], {%1,%2};" :: "r"(adr), "r"(wh.x), "r"(wh.y) : "memory");
        asm volatile("st.shared.v2.b32 [%0], {%1,%2};" :: "r"(adr + (FQL - FQH)), "r"(wl.x), "r"(wl.y) : "memory");
    }

    float m_prev0 = -1e30f, m_prev1 = -1e30f, l0 = 0.f, l1 = 0.f;
    float oacc[8][4];
#pragma unroll
    for (int t = 0; t < 8; t++)
#pragma unroll
        for (int e = 0; e < 4; e++) oacc[t][e] = 0.f;

    int row_g0 = q0 + 16 * warp_m + rg;
    int row_g1 = row_g0 + 8;

    for (int kb = 0; kb <= qb; kb++) {
        int k0 = kb * 64;
        __syncthreads();   // previous iter done with K/V/P
        // ---- K tile ----
#pragma unroll
        for (int i = 0; i < 8; i++) {
            int u = tid + i * 256;
            int r = u >> 5;
            int col = (u & 31) * 4;
            float4 v = *(const float4*)&K[(size_t)(k0 + r) * KVDIM + kvh * HEAD_DIM + col];
            uint32_t adr = sb + FKH + r * 256 + ((((col >> 3) ^ (r & 7))) << 4) + (col & 7) * 2;
            __nv_bfloat16 th[4], tl[4];
            cvt_store8(th, tl, v);
            uint2 wh = *(uint2*)th, wl = *(uint2*)tl;
            asm volatile("st.shared.v2.b32 [%0], {%1,%2};" :: "r"(adr), "r"(wh.x), "r"(wh.y) : "memory");
            asm volatile("st.shared.v2.b32 [%0], {%1,%2};" :: "r"(adr + (FKL - FKH)), "r"(wl.x), "r"(wl.y) : "memory");
        }
        // ---- V tile, transposed into Vt[d][key] (128B rows) ----
#pragma unroll
        for (int i = 0; i < 4; i++) {
            int u = tid + i * 256;          // 1024 units: 32 keypairs x 32 dgroups
            int kp = u & 31;                // keys 2kp, 2kp+1
            int d = (u >> 5) * 4;
            float4 va = *(const float4*)&V[(size_t)(k0 + 2 * kp) * KVDIM + kvh * HEAD_DIM + d];
            float4 vb = *(const float4*)&V[(size_t)(k0 + 2 * kp + 1) * KVDIM + kvh * HEAD_DIM + d];
            const float* pa = (const float*)&va;
            const float* pb = (const float*)&vb;
            int colk = 2 * kp;
#pragma unroll
            for (int j = 0; j < 4; j++) {
                int dr = d + j;
                uint32_t hi, lo;
                split_pair(pa[j], pb[j], &hi, &lo);
                uint32_t adr = sb + FVH + dr * 128 + ((((colk >> 3) ^ (dr & 7))) << 4) + (colk & 7) * 2;
                asm volatile("st.shared.b32 [%0], %1;" :: "r"(adr), "r"(hi) : "memory");
                asm volatile("st.shared.b32 [%0], %1;" :: "r"(adr + (FVL - FVH)), "r"(lo) : "memory");
            }
        }
        __syncthreads();

        // ---- S = Q K^T (3-term), warp tile 16q x 32k ----
        float sacc[4][4];
#pragma unroll
        for (int nt = 0; nt < 4; nt++)
#pragma unroll
            for (int e = 0; e < 4; e++) sacc[nt][e] = 0.f;
        int aq_row = 16 * warp_m + a_row16;
#pragma unroll
        for (int ks = 0; ks < 8; ks++) {
            uint32_t ahi[4], alo[4], khi[2][4], klo[2][4];
            uint32_t qa = sb + FQH + aq_row * 256 + ((((2 * ks + a_sel) ^ (aq_row & 7))) << 4);
            ldsm4(ahi, qa);
            ldsm4(alo, qa + (FQL - FQH));
#pragma unroll
            for (int j = 0; j < 2; j++) {
                int krow = 32 * warp_n + 16 * j + b_roff;
                uint32_t ka = sb + FKH + krow * 256 + ((((2 * ks + b_sel) ^ (krow & 7))) << 4);
                ldsm4(khi[j], ka);
                ldsm4(klo[j], ka + (FKL - FKH));
            }
#pragma unroll
            for (int nt = 0; nt < 4; nt++) {
                mma_bf16(sacc[nt], ahi, &khi[nt >> 1][(nt & 1) * 2]);
                mma_bf16(sacc[nt], ahi, &klo[nt >> 1][(nt & 1) * 2]);
                mma_bf16(sacc[nt], alo, &khi[nt >> 1][(nt & 1) * 2]);
            }
        }
        // scale + causal mask
        const float scale = 0.08838834764831845f;
#pragma unroll
        for (int nt = 0; nt < 4; nt++) {
            int cb = k0 + 32 * warp_n + 8 * nt + cg;
#pragma unroll
            for (int e = 0; e < 4; e++) sacc[nt][e] *= scale;
            if (kb == qb) {
                if (cb > row_g0) sacc[nt][0] = -1e30f;
                if (cb + 1 > row_g0) sacc[nt][1] = -1e30f;
                if (cb > row_g1) sacc[nt][2] = -1e30f;
                if (cb + 1 > row_g1) sacc[nt][3] = -1e30f;
            }
        }

        // ---- online softmax ----
        float mx0 = -1e30f, mx1 = -1e30f;
#pragma unroll
        for (int nt = 0; nt < 4; nt++) {
            mx0 = fmaxf(mx0, fmaxf(sacc[nt][0], sacc[nt][1]));
            mx1 = fmaxf(mx1, fmaxf(sacc[nt][2], sacc[nt][3]));
        }
        mx0 = fmaxf(mx0, __shfl_xor_sync(0xffffffffu, mx0, 1));
        mx0 = fmaxf(mx0, __shfl_xor_sync(0xffffffffu, mx0, 2));
        mx1 = fmaxf(mx1, __shfl_xor_sync(0xffffffffu, mx1, 1));
        mx1 = fmaxf(mx1, __shfl_xor_sync(0xffffffffu, mx1, 2));
        if ((lane & 3) == 0) {
            maxp[warp_n * 64 + 16 * warp_m + rg] = mx0;
            maxp[warp_n * 64 + 16 * warp_m + rg + 8] = mx1;
        }
        __syncthreads();
        int sidx0 = 16 * warp_m + rg, sidx1 = sidx0 + 8;
        float mb0 = fmaxf(maxp[sidx0], maxp[64 + sidx0]);
        float mb1 = fmaxf(maxp[sidx1], maxp[64 + sidx1]);
        float mn0 = fmaxf(m_prev0, mb0), mn1 = fmaxf(m_prev1, mb1);
        float corr0 = __expf(m_prev0 - mn0), corr1 = __expf(m_prev1 - mn1);

        float ps0 = 0.f, ps1 = 0.f;
#pragma unroll
        for (int nt = 0; nt < 4; nt++) {
            float p00 = __expf(sacc[nt][0] - mn0);
            float p01 = __expf(sacc[nt][1] - mn0);
            float p10 = __expf(sacc[nt][2] - mn1);
            float p11 = __expf(sacc[nt][3] - mn1);
            ps0 += p00 + p01;
            ps1 += p10 + p11;
            int col = 32 * warp_n + 8 * nt + cg;
            int r0 = 16 * warp_m + rg, r1 = r0 + 8;
            uint32_t hi, lo;
            split_pair(p00, p01, &hi, &lo);
            uint32_t a0 = sb + FPH + r0 * 128 + ((((col >> 3) ^ (r0 & 7))) << 4) + (col & 7) * 2;
            asm volatile("st.shared.b32 [%0], %1;" :: "r"(a0), "r"(hi) : "memory");
            asm volatile("st.shared.b32 [%0], %1;" :: "r"(a0 + (FPL - FPH)), "r"(lo) : "memory");
            split_pair(p10, p11, &hi, &lo);
            uint32_t a1 = sb + FPH + r1 * 128 + ((((col >> 3) ^ (r1 & 7))) << 4) + (col & 7) * 2;
            asm volatile("st.shared.b32 [%0], %1;" :: "r"(a1), "r"(hi) : "memory");
            asm volatile("st.shared.b32 [%0], %1;" :: "r"(a1 + (FPL - FPH)), "r"(lo) : "memory");
        }
        ps0 += __shfl_xor_sync(0xffffffffu, ps0, 1);
        ps0 += __shfl_xor_sync(0xffffffffu, ps0, 2);
        ps1 += __shfl_xor_sync(0xffffffffu, ps1, 1);
        ps1 += __shfl_xor_sync(0xffffffffu, ps1, 2);
        if ((lane & 3) == 0) {
            sump[warp_n * 64 + sidx0] = ps0;
            sump[warp_n * 64 + sidx1] = ps1;
        }
        // rescale O accumulators
#pragma unroll
        for (int t = 0; t < 8; t++) {
            oacc[t][0] *= corr0; oacc[t][1] *= corr0;
            oacc[t][2] *= corr1; oacc[t][3] *= corr1;
        }
        l0 *= corr0; l1 *= corr1;
        m_prev0 = mn0; m_prev1 = mn1;
        __syncthreads();
        l0 += sump[sidx0] + sump[64 + sidx0];
        l1 += sump[sidx1] + sump[64 + sidx1];

        // ---- O += P V (3-term), warp tile 16q x 64d ----
#pragma unroll
        for (int kp = 0; kp < 4; kp++) {
            uint32_t phi[4], plo[4], vhi[4][4], vlo[4][4];
            int prow = 16 * warp_m + a_row16;
            uint32_t pa = sb + FPH + prow * 128 + ((((2 * kp + a_sel) ^ (prow & 7))) << 4);
            ldsm4(phi, pa);
            ldsm4(plo, pa + (FPL - FPH));
#pragma unroll
            for (int j = 0; j < 4; j++) {
                int vrow = 64 * warp_n + 16 * j + b_roff;
                uint32_t va = sb + FVH + vrow * 128 + ((((2 * kp + b_sel) ^ (vrow & 7))) << 4);
                ldsm4(vhi[j], va);
                ldsm4(vlo[j], va + (FVL - FVH));
            }
#pragma unroll
            for (int t = 0; t < 8; t++) {
                mma_bf16(oacc[t], phi, &vhi[t >> 1][(t & 1) * 2]);
                mma_bf16(oacc[t], phi, &vlo[t >> 1][(t & 1) * 2]);
                mma_bf16(oacc[t], plo, &vhi[t >> 1][(t & 1) * 2]);
            }
        }
    }

    // ---- normalize + store ----
    float inv0 = 1.f / l0, inv1 = 1.f / l1;
#pragma unroll
    for (int t = 0; t < 8; t++) {
        int col = h * HEAD_DIM + 64 * warp_n + 8 * t + cg;
        float2 o0 = make_float2(oacc[t][0] * inv0, oacc[t][1] * inv0);
        float2 o1 = make_float2(oacc[t][2] * inv1, oacc[t][3] * inv1);
        *(float2*)&O[(size_t)row_g0 * D_MODEL + col] = o0;
        *(float2*)&O[(size_t)row_g1 * D_MODEL + col] = o1;
    }
}

// ---------------- silu(gate) * up ----------------
__global__ void silu_mul_kernel(const float* __restrict__ g, const float* __restrict__ u,
                                float* __restrict__ o, int n) {
    int i = blockIdx.x * blockDim.x + threadIdx.x;
    if (i < n) {
        float x = g[i];
        float s = x / (1.f + __expf(-x));
        o[i] = s * u[i];
    }
}

// ---------------- launch ----------------
extern "C" void kernel_launch(void* const* d_in, const int* in_sizes, int n_in,
                              void* d_out, int out_size) {
    const float* data = (const float*)d_in[0];
    const float* cosb = (const float*)d_in[2];
    const float* sinb = (const float*)d_in[3];
    const float* attn_norm_w = (const float*)d_in[4];
    const float* wq = (const float*)d_in[5];
    const float* wk = (const float*)d_in[6];
    const float* wv = (const float*)d_in[7];
    const float* wo = (const float*)d_in[8];
    const float* wq_a = (const float*)d_in[9];
    const float* wq_b = (const float*)d_in[10];
    const float* wk_a = (const float*)d_in[11];
    const float* wk_b = (const float*)d_in[12];
    const float* wv_a = (const float*)d_in[13];
    const float* wv_b = (const float*)d_in[14];
    const float* wo_a = (const float*)d_in[15];
    const float* wo_b = (const float*)d_in[16];
    const float* ffn_norm_w = (const float*)d_in[17];
    const float* w1 = (const float*)d_in[18];
    const float* w2 = (const float*)d_in[19];
    const float* w3 = (const float*)d_in[20];
    const float* w1_a = (const float*)d_in[21];
    const float* w1_b = (const float*)d_in[22];
    const float* w2_a = (const float*)d_in[23];
    const float* w2_b = (const float*)d_in[24];
    const float* w3_a = (const float*)d_in[25];
    const float* w3_b = (const float*)d_in[26];
    float* out = (float*)d_out;

    float *h, *q, *k, *v, *attn, *res1, *f, *gate, *up, *t0, *t1, *t2;
    cudaGetSymbolAddress((void**)&h, g_h);
    cudaGetSymbolAddress((void**)&q, g_q);
    cudaGetSymbolAddress((void**)&k, g_k);
    cudaGetSymbolAddress((void**)&v, g_v);
    cudaGetSymbolAddress((void**)&attn, g_attn);
    cudaGetSymbolAddress((void**)&res1, g_res1);
    cudaGetSymbolAddress((void**)&f, g_f);
    cudaGetSymbolAddress((void**)&gate, g_gate);
    cudaGetSymbolAddress((void**)&up, g_up);
    cudaGetSymbolAddress((void**)&t0, g_t0);
    cudaGetSymbolAddress((void**)&t1, g_t1);
    cudaGetSymbolAddress((void**)&t2, g_t2);

    cudaFuncSetAttribute(sgemm_lora, cudaFuncAttributeMaxDynamicSharedMemorySize,
                         GEMM_SMEM_BYTES);
    cudaFuncSetAttribute(flash_tc, cudaFuncAttributeMaxDynamicSharedMemorySize,
                         FLASH_TC_SMEM);

    // 1) attn rmsnorm
    rmsnorm_kernel<<<S_LEN, 256>>>(data, attn_norm_w, h, D_MODEL);

    // 2) q/k/v projections with fused LoRA
    lora_a_kernel<<<S_LEN, 128>>>(h, wq_a, t0, D_MODEL);
    lora_a_kernel<<<S_LEN, 128>>>(h, wk_a, t1, D_MODEL);
    lora_a_kernel<<<S_LEN, 128>>>(h, wv_a, t2, D_MODEL);
    sgemm_lora<<<dim3(D_MODEL / 128, S_LEN / 128), 256, GEMM_SMEM_BYTES>>>(h, wq, q, S_LEN, D_MODEL, D_MODEL, t0, wq_b, nullptr);
    sgemm_lora<<<dim3(KVDIM / 128, S_LEN / 128), 256, GEMM_SMEM_BYTES>>>(h, wk, k, S_LEN, KVDIM, D_MODEL, t1, wk_b, nullptr);
    sgemm_lora<<<dim3(KVDIM / 128, S_LEN / 128), 256, GEMM_SMEM_BYTES>>>(h, wv, v, S_LEN, KVDIM, D_MODEL, t2, wv_b, nullptr);

    // 3) RoPE
    rope_kernel<<<(S_LEN * N_HEADS * 64) / 256, 256>>>(q, cosb, sinb, N_HEADS);
    rope_kernel<<<(S_LEN * N_KV_HEADS * 64) / 256, 256>>>(k, cosb, sinb, N_KV_HEADS);

    // 4) attention (tensor-core flash)
    flash_tc<<<dim3(N_HEADS, S_LEN / 64), 256, FLASH_TC_SMEM>>>(q, k, v, attn);

    // 5) output projection + residual
    lora_a_kernel<<<S_LEN, 128>>>(attn, wo_a, t0, D_MODEL);
    sgemm_lora<<<dim3(D_MODEL / 128, S_LEN / 128), 256, GEMM_SMEM_BYTES>>>(attn, wo, res1, S_LEN, D_MODEL, D_MODEL, t0, wo_b, data);

    // 6) ffn rmsnorm
    rmsnorm_kernel<<<S_LEN, 256>>>(res1, ffn_norm_w, f, D_MODEL);

    // 7) gate / up
    lora_a_kernel<<<S_LEN, 128>>>(f, w1_a, t0, D_MODEL);
    lora_a_kernel<<<S_LEN, 128>>>(f, w3_a, t1, D_MODEL);
    sgemm_lora<<<dim3(FF_DIM / 128, S_LEN / 128), 256, GEMM_SMEM_BYTES>>>(f, w1, gate, S_LEN, FF_DIM, D_MODEL, t0, w1_b, nullptr);
    sgemm_lora<<<dim3(FF_DIM / 128, S_LEN / 128), 256, GEMM_SMEM_BYTES>>>(f, w3, up, S_LEN, FF_DIM, D_MODEL, t1, w3_b, nullptr);

    // 8) silu * up
    silu_mul_kernel<<<(S_LEN * FF_DIM) / 256, 256>>>(gate, up, gate, S_LEN * FF_DIM);

    // 9) down projection + residual -> out
    lora_a_kernel<<<S_LEN, 128>>>(gate, w2_a, t0, FF_DIM);
    sgemm_lora<<<dim3(D_MODEL / 128, S_LEN / 128), 256, GEMM_SMEM_BYTES>>>(gate, w2, out, S_LEN, D_MODEL, FF_DIM, t0, w2_b, res1);
}